// round 1
// baseline (speedup 1.0000x reference)
#include <cuda_runtime.h>

// ---------------------------------------------------------------------------
// Masked multi-level MSE loss:
//   for each level S in {80,40,20}:
//     M[b,y,x] = union of boxes (rasterized at resolution S) for batch b
//     L += sum( (M * (pred - true))^2 ) / (C * sum(M))
//   out = L / 3
// B=16, C=256, T=128 boxes.
// ---------------------------------------------------------------------------

#define NB 16
#define NT 128
#define NC 256

__device__ unsigned char g_mask0[NB * 80 * 80];
__device__ unsigned char g_mask1[NB * 40 * 40];
__device__ unsigned char g_mask2[NB * 20 * 20];
__device__ double g_acc[3];
__device__ int    g_cnt[3];

// ---------------------------------------------------------------------------
__global__ void init_kernel() {
    int t = threadIdx.x;
    if (t < 3) { g_acc[t] = 0.0; g_cnt[t] = 0; }
}

// ---------------------------------------------------------------------------
// One block-row (gridDim.y = level). Rasterizes all T boxes into the level
// mask; counts positive cells per block and atomically accumulates.
__global__ void mask_kernel(const float* __restrict__ bboxes,
                            const int* __restrict__ batch_idx) {
    const int lvl = blockIdx.y;
    const int S = (lvl == 0) ? 80 : (lvl == 1) ? 40 : 20;
    const int cells = NB * S * S;
    if ((int)(blockIdx.x * blockDim.x) >= cells) return;

    __shared__ short sxl[NT], sxr[NT], syt[NT], syd[NT];
    __shared__ signed char sbi[NT];

    if (threadIdx.x < NT) {
        const int t = threadIdx.x;
        const float fS = (float)S;
        int xc = (int)floorf(bboxes[t * 4 + 0] * fS);
        int yc = (int)floorf(bboxes[t * 4 + 1] * fS);
        int w  = (int)floorf(bboxes[t * 4 + 2] * fS);
        int h  = (int)floorf(bboxes[t * 4 + 3] * fS);
        int xl = max(xc - w / 2, 0);
        int yt = max(yc - h / 2, 0);
        int xr = min(xc + w / 2, S - 1);
        int yd = min(yc + h / 2, S - 1);
        sxl[t] = (short)xl; sxr[t] = (short)xr;
        syt[t] = (short)yt; syd[t] = (short)yd;
        sbi[t] = (signed char)batch_idx[t];
    }
    __syncthreads();

    const int idx = blockIdx.x * blockDim.x + threadIdx.x;
    int m = 0;
    if (idx < cells) {
        const int b = idx / (S * S);
        const int rr = idx % (S * S);
        const int y = rr / S;
        const int x = rr % S;
#pragma unroll 4
        for (int t = 0; t < NT; t++) {
            int inside = ((int)sbi[t] == b) &
                         (x >= (int)sxl[t]) & (x <= (int)sxr[t]) &
                         (y >= (int)syt[t]) & (y <= (int)syd[t]);
            m |= inside;
        }
        unsigned char* mk = (lvl == 0) ? g_mask0 : (lvl == 1) ? g_mask1 : g_mask2;
        mk[idx] = (unsigned char)m;
    }

    // count positives in this block
    unsigned bal = __ballot_sync(0xffffffffu, m != 0);
    __shared__ int wsum[8];
    const int lane = threadIdx.x & 31, warp = threadIdx.x >> 5;
    if (lane == 0) wsum[warp] = __popc(bal);
    __syncthreads();
    if (threadIdx.x == 0) {
        int s = 0;
        int nw = (blockDim.x + 31) >> 5;
        for (int i = 0; i < nw; i++) s += wsum[i];
        if (s) atomicAdd(&g_cnt[lvl], s);
    }
}

// ---------------------------------------------------------------------------
__device__ __forceinline__ float block_sum(float v) {
    __shared__ float sm[32];
#pragma unroll
    for (int o = 16; o; o >>= 1) v += __shfl_down_sync(0xffffffffu, v, o);
    const int lane = threadIdx.x & 31, warp = threadIdx.x >> 5;
    if (lane == 0) sm[warp] = v;
    __syncthreads();
    const int nw = blockDim.x >> 5;
    v = (threadIdx.x < (unsigned)nw) ? sm[threadIdx.x] : 0.f;
    if (warp == 0) {
#pragma unroll
        for (int o = 16; o; o >>= 1) v += __shfl_down_sync(0xffffffffu, v, o);
    }
    __syncthreads();  // allow smem reuse by a subsequent call
    return v;
}

template <int S>
__device__ __forceinline__ float level_sumsq(const float4* __restrict__ p,
                                             const float4* __restrict__ q,
                                             const unsigned char* __restrict__ mask,
                                             unsigned gid, unsigned stride) {
    constexpr unsigned S4  = (unsigned)S / 4;
    constexpr unsigned CH4 = (unsigned)S * S4;        // float4 per (b,c) image
    constexpr unsigned B4  = (unsigned)NC * CH4;      // float4 per batch
    constexpr unsigned N4  = (unsigned)NB * B4;       // total float4
    float acc = 0.f;
    for (unsigned i = gid; i < N4; i += stride) {
        const unsigned b = i / B4;                    // const divisor -> umulhi
        const unsigned r = i % CH4;                   // float4 index within image
        // mask byte offset for this float4: b*S*S + 4*r
        const uchar4 m = *(const uchar4*)(mask + (size_t)b * (S * S) + 4u * r);
        if ((m.x | m.y | m.z | m.w) != 0) {
            const float4 a = __ldg(&p[i]);
            const float4 c = __ldg(&q[i]);
            const float d0 = a.x - c.x, d1 = a.y - c.y;
            const float d2 = a.z - c.z, d3 = a.w - c.w;
            acc += (float)m.x * d0 * d0 + (float)m.y * d1 * d1 +
                   (float)m.z * d2 * d2 + (float)m.w * d3 * d3;
        }
    }
    return acc;
}

__global__ void reduce_kernel(const float4* __restrict__ p0, const float4* __restrict__ t0,
                              const float4* __restrict__ p1, const float4* __restrict__ t1,
                              const float4* __restrict__ p2, const float4* __restrict__ t2) {
    const unsigned gid = blockIdx.x * blockDim.x + threadIdx.x;
    const unsigned stride = gridDim.x * blockDim.x;

    float a0 = level_sumsq<80>(p0, t0, g_mask0, gid, stride);
    float a1 = level_sumsq<40>(p1, t1, g_mask1, gid, stride);
    float a2 = level_sumsq<20>(p2, t2, g_mask2, gid, stride);

    a0 = block_sum(a0);
    a1 = block_sum(a1);
    a2 = block_sum(a2);
    if (threadIdx.x == 0) {
        if (a0 != 0.f) atomicAdd(&g_acc[0], (double)a0);
        if (a1 != 0.f) atomicAdd(&g_acc[1], (double)a1);
        if (a2 != 0.f) atomicAdd(&g_acc[2], (double)a2);
    }
}

// ---------------------------------------------------------------------------
__global__ void final_kernel(float* __restrict__ out) {
    double L = g_acc[0] / (256.0 * (double)g_cnt[0]) +
               g_acc[1] / (256.0 * (double)g_cnt[1]) +
               g_acc[2] / (256.0 * (double)g_cnt[2]);
    out[0] = (float)(L / 3.0);
}

// ---------------------------------------------------------------------------
extern "C" void kernel_launch(void* const* d_in, const int* in_sizes, int n_in,
                              void* d_out, int out_size) {
    // metadata order (setup_inputs dict order):
    //   pred0, true0, pred1, true1, pred2, true2, bboxes, batch_idx, cls
    const float4* p0 = (const float4*)d_in[0];
    const float4* t0 = (const float4*)d_in[1];
    const float4* p1 = (const float4*)d_in[2];
    const float4* t1 = (const float4*)d_in[3];
    const float4* p2 = (const float4*)d_in[4];
    const float4* t2 = (const float4*)d_in[5];
    const float* bboxes = (const float*)d_in[6];
    const int* batch_idx = (const int*)d_in[7];
    // d_in[8] = cls (unused)

    init_kernel<<<1, 32>>>();

    // mask: level 0 needs 16*80*80/256 = 400 blocks; levels 1,2 exit early.
    mask_kernel<<<dim3(400, 3), 256>>>(bboxes, batch_idx);

    // streaming reduction: 148 SMs * 8 blocks * 256 threads
    reduce_kernel<<<1184, 256>>>(p0, t0, p1, t1, p2, t2);

    final_kernel<<<1, 1>>>((float*)d_out);
}